// round 2
// baseline (speedup 1.0000x reference)
#include <cuda_runtime.h>
#include <math.h>

// Problem constants
#define N_POINTS 4096
#define N_VIEWS  4
#define IMG_H    128
#define IMG_W    128
#define TOPK     5
#define R2F      0.0004f     // 0.02^2
#define RADF     0.02f
#define CAND_CAP 2048        // per-tile candidate capacity (expected ~150)

// cos(15deg), sin(15deg) in full double precision -> f32
#define CE 0.96592582628906831f
#define SE 0.25881904510252074f

// Camera axes per view (columns of R): X_view = pcd . axis + T, T = (0,0,1.5)
__constant__ float c_ax[N_VIEWS][3] = {
    {-1.f, 0.f, 0.f}, {0.f, 0.f, 1.f}, {1.f, 0.f, 0.f}, {0.f, 0.f, -1.f}};
__constant__ float c_ay[N_VIEWS][3] = {
    {0.f, CE, -SE}, {-SE, CE, 0.f}, {0.f, CE, SE}, {SE, CE, 0.f}};
__constant__ float c_az[N_VIEWS][3] = {
    {0.f, -SE, -CE}, {-CE, -SE, 0.f}, {0.f, -SE, CE}, {CE, -SE, 0.f}};

// Per-view transformed points: (px, py, pz_ndc, color)
__device__ float4 g_pts[N_VIEWS][N_POINTS];

__global__ void prep_kernel(const float* __restrict__ pcd,
                            const float* __restrict__ displace,
                            const float* __restrict__ init_colors,
                            float* __restrict__ out_colors) {
    int n = blockIdx.x * blockDim.x + threadIdx.x;
    if (n >= N_POINTS) return;
    float x = pcd[3 * n + 0];
    float y = pcd[3 * n + 1];
    float z = pcd[3 * n + 2];
    float col = 1.0f / (1.0f + expf(-(init_colors[n] + displace[n])));
    out_colors[n] = col;
#pragma unroll
    for (int v = 0; v < N_VIEWS; v++) {
        float px = x * c_ax[v][0] + y * c_ax[v][1] + z * c_ax[v][2];
        float py = x * c_ay[v][0] + y * c_ay[v][1] + z * c_ay[v][2];
        float zv = x * c_az[v][0] + y * c_az[v][1] + z * c_az[v][2] + 1.5f;
        float pz = (zv - 0.01f) / 99.99f;
        g_pts[v][n] = make_float4(px, py, pz, col);
    }
}

__global__ void __launch_bounds__(256) raster_kernel(float* __restrict__ out) {
    __shared__ float4 s_cand[CAND_CAP];
    __shared__ int s_cnt;

    const int v  = blockIdx.z;
    const int x0 = blockIdx.x * 16;
    const int y0 = blockIdx.y * 16;
    const int tid = threadIdx.y * 16 + threadIdx.x;

    if (tid == 0) s_cnt = 0;
    __syncthreads();

    // NDC: xf = 1 - (2*xi+1)/128, decreasing in xi (same for yf)
    const float inv128 = 0.0078125f;
    float xhi = 1.0f - (float)(2 * x0 + 1) * inv128 + RADF;
    float xlo = 1.0f - (float)(2 * (x0 + 15) + 1) * inv128 - RADF;
    float yhi = 1.0f - (float)(2 * y0 + 1) * inv128 + RADF;
    float ylo = 1.0f - (float)(2 * (y0 + 15) + 1) * inv128 - RADF;

    // Tile candidate filtering (all 256 threads sweep the 4096 points)
    for (int i = tid; i < N_POINTS; i += 256) {
        float4 p = g_pts[v][i];
        if (p.z > 0.0f && p.x >= xlo && p.x <= xhi && p.y >= ylo && p.y <= yhi) {
            int s = atomicAdd(&s_cnt, 1);
            if (s < CAND_CAP) s_cand[s] = p;
        }
    }
    __syncthreads();
    int m = s_cnt;
    if (m > CAND_CAP) m = CAND_CAP;

    const int xi = x0 + threadIdx.x;
    const int yi = y0 + threadIdx.y;
    const float xf = 1.0f - (float)(2 * xi + 1) * inv128;
    const float yf = 1.0f - (float)(2 * yi + 1) * inv128;

    const float INF = __int_as_float(0x7f800000);
    float zk[TOPK], ak[TOPK], ck[TOPK];
#pragma unroll
    for (int k = 0; k < TOPK; k++) { zk[k] = INF; ak[k] = 0.0f; ck[k] = 0.0f; }

    // Per-pixel scan of the shared candidate list (broadcast reads)
    for (int j = 0; j < m; j++) {
        float4 p = s_cand[j];
        float dx = p.x - xf;
        float dy = p.y - yf;
        float d2 = dx * dx + dy * dy;
        if (d2 < R2F) {
            float nz = p.z;
            float na = 1.0f - d2 / R2F;
            float nc = p.w;
            // sorted insertion by z ascending (keep 5 smallest)
#pragma unroll
            for (int k = 0; k < TOPK; k++) {
                if (nz < zk[k]) {
                    float t;
                    t = zk[k]; zk[k] = nz; nz = t;
                    t = ak[k]; ak[k] = na; na = t;
                    t = ck[k]; ck[k] = nc; nc = t;
                }
            }
        }
    }

    // Front-to-back over-composite (empty slots have alpha = 0)
    float trans = 1.0f, pix = 0.0f;
#pragma unroll
    for (int k = 0; k < TOPK; k++) {
        pix += ak[k] * trans * ck[k];
        trans *= (1.0f - ak[k]);
    }

    int base = (((v * IMG_H) + yi) * IMG_W + xi) * 3;
    out[base + 0] = pix;
    out[base + 1] = pix;
    out[base + 2] = pix;
}

extern "C" void kernel_launch(void* const* d_in, const int* in_sizes, int n_in,
                              void* d_out, int out_size) {
    const float* pcd         = (const float*)d_in[0];
    const float* displace    = (const float*)d_in[1];
    const float* init_colors = (const float*)d_in[2];
    float* out = (float*)d_out;

    // colors_ tail lives after the 4*128*128*3 image block
    float* out_colors = out + (size_t)N_VIEWS * IMG_H * IMG_W * 3;

    prep_kernel<<<(N_POINTS + 255) / 256, 256>>>(pcd, displace, init_colors, out_colors);

    dim3 grid(IMG_W / 16, IMG_H / 16, N_VIEWS);
    dim3 block(16, 16);
    raster_kernel<<<grid, block>>>(out);
}